// round 1
// baseline (speedup 1.0000x reference)
#include <cuda_runtime.h>
#include <math.h>

// Problem constants
#define N_TOK 4096
#define DIMD  1024
#define HID   4096
#define OUTD  1024
#define NE    8
#define RMAX  (2*N_TOK)   // total expert-row assignments (exactly 2 per token)

// ---------------- scratch (static device globals; no allocation) ----------------
__device__ float g_hbuf[(size_t)RMAX * HID];   // 128 MB: GEMM1 outputs (gathered rows)
__device__ float g_ybuf[(size_t)RMAX * OUTD];  //  32 MB: GEMM2 outputs
__device__ int   g_perm[RMAX];                 // gathered row -> token id
__device__ float g_wgt[RMAX];                  // gathered row -> combine weight
__device__ int   g_rowpos[N_TOK * 2];          // token -> its two gathered rows
__device__ int   g_sel[N_TOK * 2];
__device__ float g_w[N_TOK * 2];
__device__ int   g_cnt[NE];
__device__ int   g_off[NE];
__device__ int   g_cur[NE];

// ---------------- init: zero per-launch counters ----------------
__global__ void init_kernel() {
    int t = threadIdx.x;
    if (t < NE) { g_cnt[t] = 0; g_cur[t] = 0; }
}

// ---------------- gate: logits -> relu -> top2 (jax tie-break) -> 2-way softmax ----------------
__global__ void gate_kernel(const float* __restrict__ x, const float* __restrict__ Wg) {
    __shared__ float red[256][NE];
    const int n   = blockIdx.x;
    const int tid = threadIdx.x;
    const float* xr = x + (size_t)n * DIMD;

    float acc[NE];
#pragma unroll
    for (int e = 0; e < NE; e++) acc[e] = 0.f;

    for (int d = tid; d < DIMD; d += 256) {
        float xv = xr[d];
        const float4* wr = (const float4*)(Wg + (size_t)d * NE);
        float4 w0 = wr[0], w1 = wr[1];
        acc[0] += xv * w0.x; acc[1] += xv * w0.y; acc[2] += xv * w0.z; acc[3] += xv * w0.w;
        acc[4] += xv * w1.x; acc[5] += xv * w1.y; acc[6] += xv * w1.z; acc[7] += xv * w1.w;
    }
#pragma unroll
    for (int e = 0; e < NE; e++) red[tid][e] = acc[e];
    __syncthreads();
    for (int s = 128; s > 0; s >>= 1) {
        if (tid < s) {
#pragma unroll
            for (int e = 0; e < NE; e++) red[tid][e] += red[tid + s][e];
        }
        __syncthreads();
    }

    if (tid == 0) {
        float v[NE];
#pragma unroll
        for (int e = 0; e < NE; e++) v[e] = fmaxf(red[0][e], 0.f);   // relu(logits)
        // Stable top-2: strict '>' keeps the LOWEST index on ties, matching jax.lax.top_k.
        int e0 = 0; float p0 = v[0];
        int e1 = -1; float p1 = -1.f;
#pragma unroll
        for (int e = 1; e < NE; e++) {
            if (v[e] > p0)      { p1 = p0; e1 = e0; p0 = v[e]; e0 = e; }
            else if (v[e] > p1) { p1 = v[e]; e1 = e; }
        }
        // renormalized top-2 softmax == 2-way softmax of the relu'd logits
        float w0 = 1.f / (1.f + expf(p1 - p0));
        float w1 = 1.f - w0;
        g_sel[2*n]   = e0; g_sel[2*n+1] = e1;
        g_w[2*n]     = w0; g_w[2*n+1]   = w1;
        atomicAdd(&g_cnt[e0], 1);
        atomicAdd(&g_cnt[e1], 1);
    }
}

// ---------------- offsets: tiny prefix sum over 8 experts ----------------
__global__ void offsets_kernel() {
    if (threadIdx.x == 0) {
        int o = 0;
        for (int e = 0; e < NE; e++) { g_off[e] = o; o += g_cnt[e]; g_cur[e] = 0; }
    }
}

// ---------------- scatter: build per-expert gathered row lists ----------------
__global__ void scatter_kernel() {
    int n = blockIdx.x * blockDim.x + threadIdx.x;
    if (n >= N_TOK) return;
#pragma unroll
    for (int k = 0; k < 2; k++) {
        int e = g_sel[2*n + k];
        int p = atomicAdd(&g_cur[e], 1);
        int r = g_off[e] + p;
        g_perm[r] = n;
        g_wgt[r]  = g_w[2*n + k];
        g_rowpos[2*n + k] = r;
    }
}

// ---------------- tiled fp32 GEMM: 128x128x16, 256 threads, 8x8 per thread ----------------
// FIRST=true : C1 = relu(gather(x) @ W1[e] + b1[e])  -> g_hbuf     (KD=1024, ND=4096)
// FIRST=false: C2 = relu(g_hbuf  @ W2[e] + b2[e])    -> g_ybuf     (KD=4096, ND=1024)
// lda == KD in both cases.
template<int KD, int ND, bool FIRST>
__global__ __launch_bounds__(256, 2)
void gemm_kernel(const float* __restrict__ xsrc,
                 const float* __restrict__ Wbase,
                 const float* __restrict__ biasBase)
{
    __shared__ float As[16][128];
    __shared__ float Bs[16][128];

    const int e    = blockIdx.z;
    const int cnt  = g_cnt[e];
    const int row0 = blockIdx.y * 128;
    if (row0 >= cnt) return;
    const int base = g_off[e];
    const int col0 = blockIdx.x * 128;

    const float* Asrc = FIRST ? xsrc : (const float*)g_hbuf;
    float*       C    = FIRST ? g_hbuf : g_ybuf;

    const float* B    = Wbase   + (size_t)e * KD * ND + col0;
    const float* bias = biasBase + (size_t)e * ND + col0;

    const int tid = threadIdx.x;
    const int tx  = tid & 15;
    const int ty  = tid >> 4;

    // A loader: two rows per thread (aRow, aRow+64), 4 consecutive k each
    const int aRow = tid >> 2;        // 0..63
    const int aK   = (tid & 3) * 4;   // 0,4,8,12
    const int lrA0 = row0 + aRow;
    const int lrA1 = row0 + aRow + 64;
    const int crA0 = (lrA0 < cnt) ? lrA0 : 0;   // clamp to stay in-bounds; rows never stored
    const int crA1 = (lrA1 < cnt) ? lrA1 : 0;
    const float* ap0;
    const float* ap1;
    if (FIRST) {
        ap0 = Asrc + (size_t)g_perm[base + crA0] * KD;
        ap1 = Asrc + (size_t)g_perm[base + crA1] * KD;
    } else {
        ap0 = Asrc + (size_t)(base + crA0) * KD;
        ap1 = Asrc + (size_t)(base + crA1) * KD;
    }

    // B loader: two k-rows per thread (bK, bK+8), 4 consecutive cols
    const int bK = tid >> 5;          // 0..7
    const int bC = (tid & 31) * 4;    // 0..124
    const float* bp = B + (size_t)bK * ND + bC;

    float acc[8][8];
#pragma unroll
    for (int i = 0; i < 8; i++)
#pragma unroll
        for (int j = 0; j < 8; j++) acc[i][j] = 0.f;

    // prologue fetch (k-tile 0)
    float4 av0 = *(const float4*)(ap0 + aK);
    float4 av1 = *(const float4*)(ap1 + aK);
    float4 bv0 = *(const float4*)(bp);
    float4 bv1 = *(const float4*)(bp + (size_t)8 * ND);

    const int KT = KD / 16;
    for (int kt = 0; kt < KT; kt++) {
        // stage current tile to smem
        As[aK+0][aRow]      = av0.x; As[aK+1][aRow]      = av0.y;
        As[aK+2][aRow]      = av0.z; As[aK+3][aRow]      = av0.w;
        As[aK+0][aRow+64]   = av1.x; As[aK+1][aRow+64]   = av1.y;
        As[aK+2][aRow+64]   = av1.z; As[aK+3][aRow+64]   = av1.w;
        *(float4*)&Bs[bK][bC]     = bv0;
        *(float4*)&Bs[bK+8][bC]   = bv1;
        __syncthreads();

        // prefetch next tile into registers (hide LDG under compute)
        if (kt + 1 < KT) {
            const int k0 = (kt + 1) * 16;
            av0 = *(const float4*)(ap0 + k0 + aK);
            av1 = *(const float4*)(ap1 + k0 + aK);
            bv0 = *(const float4*)(bp + (size_t)k0 * ND);
            bv1 = *(const float4*)(bp + (size_t)(k0 + 8) * ND);
        }

        // compute 16 k-steps
#pragma unroll
        for (int k = 0; k < 16; k++) {
            const float4* As4 = (const float4*)As[k];
            const float4* Bs4 = (const float4*)Bs[k];
            float4 a0 = As4[ty],      a1 = As4[ty + 16];
            float4 b0 = Bs4[tx],      b1 = Bs4[tx + 16];
            float a[8] = {a0.x,a0.y,a0.z,a0.w,a1.x,a1.y,a1.z,a1.w};
            float b[8] = {b0.x,b0.y,b0.z,b0.w,b1.x,b1.y,b1.z,b1.w};
#pragma unroll
            for (int i = 0; i < 8; i++)
#pragma unroll
                for (int j = 0; j < 8; j++)
                    acc[i][j] += a[i] * b[j];
        }
        __syncthreads();
    }

    // epilogue: bias + relu + store
    float4 bb0 = *(const float4*)(bias + tx*4);
    float4 bb1 = *(const float4*)(bias + tx*4 + 64);
    float bb[8] = {bb0.x,bb0.y,bb0.z,bb0.w,bb1.x,bb1.y,bb1.z,bb1.w};

#pragma unroll
    for (int i = 0; i < 8; i++) {
        const int m  = (i < 4) ? (ty*4 + i) : (64 + ty*4 + (i - 4));
        const int lr = row0 + m;
        if (lr < cnt) {
            float* cp = C + (size_t)(base + lr) * ND + col0;
            float4 o0, o1;
            o0.x = fmaxf(acc[i][0] + bb[0], 0.f);
            o0.y = fmaxf(acc[i][1] + bb[1], 0.f);
            o0.z = fmaxf(acc[i][2] + bb[2], 0.f);
            o0.w = fmaxf(acc[i][3] + bb[3], 0.f);
            o1.x = fmaxf(acc[i][4] + bb[4], 0.f);
            o1.y = fmaxf(acc[i][5] + bb[5], 0.f);
            o1.z = fmaxf(acc[i][6] + bb[6], 0.f);
            o1.w = fmaxf(acc[i][7] + bb[7], 0.f);
            *(float4*)(cp + tx*4)      = o0;
            *(float4*)(cp + tx*4 + 64) = o1;
        }
    }
}

// ---------------- combine: out[n] = w0*y[row0(n)] + w1*y[row1(n)] ----------------
__global__ void combine_kernel(float* __restrict__ out) {
    int gid = blockIdx.x * blockDim.x + threadIdx.x;    // over N*O/4
    if (gid >= N_TOK * OUTD / 4) return;
    int n = gid / (OUTD / 4);
    int c = (gid % (OUTD / 4)) * 4;
    int r0 = g_rowpos[2*n], r1 = g_rowpos[2*n + 1];
    float w0 = g_wgt[r0], w1 = g_wgt[r1];
    float4 y0 = *(const float4*)(g_ybuf + (size_t)r0 * OUTD + c);
    float4 y1 = *(const float4*)(g_ybuf + (size_t)r1 * OUTD + c);
    float4 o;
    o.x = w0*y0.x + w1*y1.x;
    o.y = w0*y0.y + w1*y1.y;
    o.z = w0*y0.z + w1*y1.z;
    o.w = w0*y0.w + w1*y1.w;
    *(float4*)(out + (size_t)n * OUTD + c) = o;
}

// ---------------- launch ----------------
extern "C" void kernel_launch(void* const* d_in, const int* in_sizes, int n_in,
                              void* d_out, int out_size) {
    const float* x  = (const float*)d_in[0];
    const float* Wg = (const float*)d_in[1];
    const float* W1 = (const float*)d_in[2];
    const float* b1 = (const float*)d_in[3];
    const float* W2 = (const float*)d_in[4];
    const float* b2 = (const float*)d_in[5];
    float* out = (float*)d_out;

    init_kernel<<<1, 32>>>();
    gate_kernel<<<N_TOK, 256>>>(x, Wg);
    offsets_kernel<<<1, 1>>>();
    scatter_kernel<<<(N_TOK + 255) / 256, 256>>>();

    // GEMM1: relu(gather(x) @ W1[e] + b1[e]) -> g_hbuf
    {
        dim3 grid(HID / 128, N_TOK / 128, NE);   // (32, 32, 8); inactive row-tiles early-exit
        gemm_kernel<DIMD, HID, true><<<grid, 256>>>(x, W1, b1);
    }
    // GEMM2: relu(g_hbuf @ W2[e] + b2[e]) -> g_ybuf
    {
        dim3 grid(OUTD / 128, N_TOK / 128, NE);  // (8, 32, 8)
        gemm_kernel<HID, OUTD, false><<<grid, 256>>>(x, W2, b2);
    }
    combine_kernel<<<(N_TOK * OUTD / 4 + 255) / 256, 256>>>(out);
}

// round 2
// speedup vs baseline: 2.7398x; 2.7398x over previous
#include <cuda_runtime.h>
#include <math.h>

// Problem constants
#define N_TOK 4096
#define DIMD  1024
#define HID   4096
#define OUTD  1024
#define NE    8
#define RMAX  (2*N_TOK)

// ---------------- scratch ----------------
__device__ float g_hbuf[(size_t)RMAX * HID];   // 128 MB
__device__ float g_ybuf[(size_t)RMAX * OUTD];  //  32 MB
__device__ int   g_perm[RMAX];
__device__ float g_wgt[RMAX];
__device__ int   g_rowpos[N_TOK * 2];
__device__ int   g_sel[N_TOK * 2];
__device__ float g_w[N_TOK * 2];
__device__ int   g_cnt[NE];
__device__ int   g_off[NE];
__device__ int   g_cur[NE];

__global__ void init_kernel() {
    int t = threadIdx.x;
    if (t < NE) { g_cnt[t] = 0; g_cur[t] = 0; }
}

// ---------------- gate ----------------
__global__ void gate_kernel(const float* __restrict__ x, const float* __restrict__ Wg) {
    __shared__ float red[256][NE];
    const int n   = blockIdx.x;
    const int tid = threadIdx.x;
    const float* xr = x + (size_t)n * DIMD;

    float acc[NE];
#pragma unroll
    for (int e = 0; e < NE; e++) acc[e] = 0.f;

    for (int d = tid; d < DIMD; d += 256) {
        float xv = xr[d];
        const float4* wr = (const float4*)(Wg + (size_t)d * NE);
        float4 w0 = wr[0], w1 = wr[1];
        acc[0] += xv * w0.x; acc[1] += xv * w0.y; acc[2] += xv * w0.z; acc[3] += xv * w0.w;
        acc[4] += xv * w1.x; acc[5] += xv * w1.y; acc[6] += xv * w1.z; acc[7] += xv * w1.w;
    }
#pragma unroll
    for (int e = 0; e < NE; e++) red[tid][e] = acc[e];
    __syncthreads();
    for (int s = 128; s > 0; s >>= 1) {
        if (tid < s) {
#pragma unroll
            for (int e = 0; e < NE; e++) red[tid][e] += red[tid + s][e];
        }
        __syncthreads();
    }

    if (tid == 0) {
        float v[NE];
#pragma unroll
        for (int e = 0; e < NE; e++) v[e] = fmaxf(red[0][e], 0.f);
        int e0 = 0; float p0 = v[0];
        int e1 = -1; float p1 = -1.f;
#pragma unroll
        for (int e = 1; e < NE; e++) {
            if (v[e] > p0)      { p1 = p0; e1 = e0; p0 = v[e]; e0 = e; }
            else if (v[e] > p1) { p1 = v[e]; e1 = e; }
        }
        float w0 = 1.f / (1.f + expf(p1 - p0));
        float w1 = 1.f - w0;
        g_sel[2*n]   = e0; g_sel[2*n+1] = e1;
        g_w[2*n]     = w0; g_w[2*n+1]   = w1;
        atomicAdd(&g_cnt[e0], 1);
        atomicAdd(&g_cnt[e1], 1);
    }
}

__global__ void offsets_kernel() {
    if (threadIdx.x == 0) {
        int o = 0;
        for (int e = 0; e < NE; e++) { g_off[e] = o; o += g_cnt[e]; g_cur[e] = 0; }
    }
}

__global__ void scatter_kernel() {
    int n = blockIdx.x * blockDim.x + threadIdx.x;
    if (n >= N_TOK) return;
#pragma unroll
    for (int k = 0; k < 2; k++) {
        int e = g_sel[2*n + k];
        int p = atomicAdd(&g_cur[e], 1);
        int r = g_off[e] + p;
        g_perm[r] = n;
        g_wgt[r]  = g_w[2*n + k];
        g_rowpos[2*n + k] = r;
    }
}

// ---------------- tensor-core tf32 GEMM ----------------
// CTA tile 128x128, 4 warps (2x2), warp tile 64x64 via m16n8k8 tf32 mma.
// 3-stage cp.async pipeline, k-tile 32.
// smem: A [128][36] (stride 36 -> LDS bank = lane, conflict-free)
//       B [32][136] k-major (stride 136 -> bank = 8*(k%4)+lane/4, conflict-free)

#define ASTRIDE 36
#define BSTRIDE 136
#define ASZ (128*ASTRIDE)          // 4608 floats
#define BSZ (32*BSTRIDE)           // 4352 floats
#define STG (ASZ + BSZ)            // 8960 floats per stage
#define SMEM_BYTES (3*STG*4)       // 107520 B

__device__ __forceinline__ void cp16(float* dst, const float* src) {
    unsigned sd = (unsigned)__cvta_generic_to_shared(dst);
    asm volatile("cp.async.cg.shared.global [%0], [%1], 16;" :: "r"(sd), "l"(src));
}
__device__ __forceinline__ void cp_commit() {
    asm volatile("cp.async.commit_group;");
}
__device__ __forceinline__ unsigned f2tf32(float f) {
    unsigned u; asm("cvt.rna.tf32.f32 %0, %1;" : "=r"(u) : "f"(f)); return u;
}
__device__ __forceinline__ void mma_tf32(float4& c, const unsigned a[4], const unsigned b[2]) {
    asm volatile("mma.sync.aligned.m16n8k8.row.col.f32.tf32.tf32.f32 "
        "{%0,%1,%2,%3}, {%4,%5,%6,%7}, {%8,%9}, {%0,%1,%2,%3};"
        : "+f"(c.x), "+f"(c.y), "+f"(c.z), "+f"(c.w)
        : "r"(a[0]), "r"(a[1]), "r"(a[2]), "r"(a[3]), "r"(b[0]), "r"(b[1]));
}

template<int KD, int ND, bool FIRST>
__global__ __launch_bounds__(128)
void gemm_tc(const float* __restrict__ xsrc,
             const float* __restrict__ Wbase,
             const float* __restrict__ biasBase)
{
    extern __shared__ float smem[];

    const int e    = blockIdx.z;
    const int cnt  = g_cnt[e];
    const int row0 = blockIdx.x * 128;      // m fastest -> concurrent CTAs share B slice in L2
    if (row0 >= cnt) return;
    const int base = g_off[e];
    const int col0 = blockIdx.y * 128;

    const float* Asrc = FIRST ? xsrc : (const float*)g_hbuf;
    float*       C    = FIRST ? g_hbuf : g_ybuf;
    const float* B    = Wbase    + (size_t)e * KD * ND + col0;
    const float* bias = biasBase + (size_t)e * ND + col0;

    const int tid  = threadIdx.x;
    const int warp = tid >> 5, lane = tid & 31;
    const int wm   = warp >> 1, wn = warp & 1;
    const int lq   = lane >> 2, lr = lane & 3;

    // ---- loader setup ----
    // A: thread handles rows (tid>>3)+16i, 16B chunk j = tid&7 (k offset j*4)
    const int jA = (tid & 7) * 4;
    int aoff[8];                              // element offsets into Asrc (fits in int)
#pragma unroll
    for (int i = 0; i < 8; i++) {
        int r  = (tid >> 3) + 16*i;
        int gr = row0 + r;
        int cr = (gr < cnt) ? gr : 0;
        if (FIRST) aoff[i] = g_perm[base + cr] * KD + jA;
        else       aoff[i] = (base + cr) * KD + jA;
    }
    // B: thread handles k-rows (tid>>5)+4i, 16B col chunk tid&31
    const int jB = (tid & 31) * 4;
    const float* bptr = B + (size_t)(tid >> 5) * ND + jB;

    float4 c[4][8];
#pragma unroll
    for (int f = 0; f < 4; f++)
#pragma unroll
        for (int g = 0; g < 8; g++) c[f][g] = make_float4(0.f, 0.f, 0.f, 0.f);

    const int KT = KD / 32;

    // issue one k-tile into stage buffer
    auto issue = [&](int kt, int buf) {
        float* As = smem + buf * STG;
        float* Bs = As + ASZ;
        const int k0f = kt * 32;
#pragma unroll
        for (int i = 0; i < 8; i++)
            cp16(As + ((tid >> 3) + 16*i) * ASTRIDE + jA, Asrc + aoff[i] + k0f);
#pragma unroll
        for (int i = 0; i < 8; i++)
            cp16(Bs + ((tid >> 5) + 4*i) * BSTRIDE + jB, bptr + (size_t)(k0f + 4*i) * ND);
    };

    issue(0, 0); cp_commit();
    issue(1, 1); cp_commit();

    for (int kt = 0; kt < KT; kt++) {
        if (kt + 2 < KT) { issue(kt + 2, (kt + 2) % 3); cp_commit(); }

        const int rem = KT - 1 - kt;
        if (rem >= 2)      asm volatile("cp.async.wait_group 2;");
        else if (rem == 1) asm volatile("cp.async.wait_group 1;");
        else               asm volatile("cp.async.wait_group 0;");
        __syncthreads();

        const float* As = smem + (kt % 3) * STG;
        const float* Bs = As + ASZ;

#pragma unroll
        for (int ks = 0; ks < 4; ks++) {
            const int k0 = ks * 8;
            unsigned a[4][4], b[8][2];
#pragma unroll
            for (int f = 0; f < 4; f++) {
                const int r = wm*64 + f*16 + lq;
                a[f][0] = f2tf32(As[ r      * ASTRIDE + k0 + lr    ]);
                a[f][1] = f2tf32(As[(r + 8) * ASTRIDE + k0 + lr    ]);
                a[f][2] = f2tf32(As[ r      * ASTRIDE + k0 + lr + 4]);
                a[f][3] = f2tf32(As[(r + 8) * ASTRIDE + k0 + lr + 4]);
            }
#pragma unroll
            for (int g = 0; g < 8; g++) {
                const int n = wn*64 + g*8 + lq;
                b[g][0] = f2tf32(Bs[(k0 + lr    ) * BSTRIDE + n]);
                b[g][1] = f2tf32(Bs[(k0 + lr + 4) * BSTRIDE + n]);
            }
#pragma unroll
            for (int f = 0; f < 4; f++)
#pragma unroll
                for (int g = 0; g < 8; g++)
                    mma_tf32(c[f][g], a[f], b[g]);
        }
        __syncthreads();
    }

    // ---- epilogue: bias + relu + store ----
    float2 bb[8];
#pragma unroll
    for (int g = 0; g < 8; g++)
        bb[g] = *(const float2*)(bias + wn*64 + g*8 + 2*lr);

#pragma unroll
    for (int f = 0; f < 4; f++) {
        const int gr0 = row0 + wm*64 + f*16 + lq;
        const int gr1 = gr0 + 8;
#pragma unroll
        for (int g = 0; g < 8; g++) {
            const int col = col0 + wn*64 + g*8 + 2*lr;
            float4 cc = c[f][g];
            if (gr0 < cnt) {
                float2 o;
                o.x = fmaxf(cc.x + bb[g].x, 0.f);
                o.y = fmaxf(cc.y + bb[g].y, 0.f);
                *(float2*)(C + (size_t)(base + gr0) * ND + col) = o;
            }
            if (gr1 < cnt) {
                float2 o;
                o.x = fmaxf(cc.z + bb[g].x, 0.f);
                o.y = fmaxf(cc.w + bb[g].y, 0.f);
                *(float2*)(C + (size_t)(base + gr1) * ND + col) = o;
            }
        }
    }
}

// ---------------- combine ----------------
__global__ void combine_kernel(float* __restrict__ out) {
    int gid = blockIdx.x * blockDim.x + threadIdx.x;
    if (gid >= N_TOK * OUTD / 4) return;
    int n = gid / (OUTD / 4);
    int c = (gid % (OUTD / 4)) * 4;
    int r0 = g_rowpos[2*n], r1 = g_rowpos[2*n + 1];
    float w0 = g_wgt[r0], w1 = g_wgt[r1];
    float4 y0 = *(const float4*)(g_ybuf + (size_t)r0 * OUTD + c);
    float4 y1 = *(const float4*)(g_ybuf + (size_t)r1 * OUTD + c);
    float4 o;
    o.x = w0*y0.x + w1*y1.x;
    o.y = w0*y0.y + w1*y1.y;
    o.z = w0*y0.z + w1*y1.z;
    o.w = w0*y0.w + w1*y1.w;
    *(float4*)(out + (size_t)n * OUTD + c) = o;
}

// ---------------- launch ----------------
extern "C" void kernel_launch(void* const* d_in, const int* in_sizes, int n_in,
                              void* d_out, int out_size) {
    const float* x  = (const float*)d_in[0];
    const float* Wg = (const float*)d_in[1];
    const float* W1 = (const float*)d_in[2];
    const float* b1 = (const float*)d_in[3];
    const float* W2 = (const float*)d_in[4];
    const float* b2 = (const float*)d_in[5];
    float* out = (float*)d_out;

    cudaFuncSetAttribute(gemm_tc<DIMD, HID, true>,
                         cudaFuncAttributeMaxDynamicSharedMemorySize, SMEM_BYTES);
    cudaFuncSetAttribute(gemm_tc<HID, OUTD, false>,
                         cudaFuncAttributeMaxDynamicSharedMemorySize, SMEM_BYTES);

    init_kernel<<<1, 32>>>();
    gate_kernel<<<N_TOK, 256>>>(x, Wg);
    offsets_kernel<<<1, 1>>>();
    scatter_kernel<<<(N_TOK + 255) / 256, 256>>>();

    {
        dim3 grid(32, HID / 128, NE);    // (m, n, e) — m fastest
        gemm_tc<DIMD, HID, true><<<grid, 128, SMEM_BYTES>>>(x, W1, b1);
    }
    {
        dim3 grid(32, OUTD / 128, NE);
        gemm_tc<HID, OUTD, false><<<grid, 128, SMEM_BYTES>>>(x, W2, b2);
    }
    combine_kernel<<<(N_TOK * OUTD / 4 + 255) / 256, 256>>>(out);
}

// round 4
// speedup vs baseline: 5.2338x; 1.9103x over previous
#include <cuda_runtime.h>
#include <cuda_fp16.h>
#include <math.h>
#include <stdint.h>

#define N_TOK 4096
#define DIMD  1024
#define HID   4096
#define OUTD  1024
#define NE    8
#define RMAX  (2*N_TOK)

// ---------------- scratch (static device globals) ----------------
__device__ __half g_xh[(size_t)RMAX * DIMD];    // 16 MB gathered tokens (fp16)
__device__ __half g_hh[(size_t)RMAX * HID];     // 64 MB GEMM1 out (fp16)
__device__ float  g_ybuf[(size_t)RMAX * OUTD];  // 32 MB GEMM2 out (fp32)
__device__ __half g_w1h[(size_t)NE * DIMD * HID];  // 64 MB
__device__ __half g_w2h[(size_t)NE * HID * OUTD];  // 64 MB
__device__ int   g_perm[RMAX];
__device__ float g_wgt[RMAX];
__device__ int   g_rowpos[N_TOK * 2];
__device__ int   g_sel[N_TOK * 2];
__device__ float g_w[N_TOK * 2];
__device__ int   g_cnt[NE];
__device__ int   g_off[NE];
__device__ int   g_cur[NE];

// ---------------- helpers ----------------
__device__ __forceinline__ void cp16(void* dst, const void* src) {
    unsigned sd = (unsigned)__cvta_generic_to_shared(dst);
    asm volatile("cp.async.cg.shared.global [%0], [%1], 16;" :: "r"(sd), "l"(src));
}
__device__ __forceinline__ uint32_t smem_u32(const void* p) {
    uint32_t a;
    asm("{ .reg .u64 t; cvta.to.shared.u64 t, %1; cvt.u32.u64 %0, t; }" : "=r"(a) : "l"(p));
    return a;
}
__device__ __forceinline__ void ldm4(uint32_t r[4], uint32_t addr) {
    asm volatile("ldmatrix.sync.aligned.m8n8.x4.shared.b16 {%0,%1,%2,%3}, [%4];"
        : "=r"(r[0]), "=r"(r[1]), "=r"(r[2]), "=r"(r[3]) : "r"(addr));
}
__device__ __forceinline__ void ldm4t(uint32_t r[4], uint32_t addr) {
    asm volatile("ldmatrix.sync.aligned.m8n8.x4.trans.shared.b16 {%0,%1,%2,%3}, [%4];"
        : "=r"(r[0]), "=r"(r[1]), "=r"(r[2]), "=r"(r[3]) : "r"(addr));
}
__device__ __forceinline__ void mma16816(float c[4], const uint32_t a[4], const uint32_t* b) {
    asm volatile("mma.sync.aligned.m16n8k16.row.col.f32.f16.f16.f32 "
        "{%0,%1,%2,%3}, {%4,%5,%6,%7}, {%8,%9}, {%0,%1,%2,%3};"
        : "+f"(c[0]), "+f"(c[1]), "+f"(c[2]), "+f"(c[3])
        : "r"(a[0]), "r"(a[1]), "r"(a[2]), "r"(a[3]), "r"(b[0]), "r"(b[1]));
}

#define SW128(x) ((x) ^ (((x) >> 3) & 0x70))

#define STAGE   49152                       // A: 16KB (128 rows x 128B) + B: 32KB (64 k-rows x 512B)
#define SMEM_TOTAL (4 * STAGE)              // 196608

// ---------------- init ----------------
__global__ void init_kernel() {
    int t = threadIdx.x;
    if (t < NE) { g_cnt[t] = 0; g_cur[t] = 0; }
}

// ---------------- gate (fp32, routing must match reference exactly) ----------------
__global__ void gate_kernel(const float* __restrict__ x, const float* __restrict__ Wg) {
    __shared__ float red[256][NE];
    const int n = blockIdx.x, tid = threadIdx.x;
    const float* xr = x + (size_t)n * DIMD;
    float acc[NE];
#pragma unroll
    for (int e = 0; e < NE; e++) acc[e] = 0.f;
    for (int d = tid; d < DIMD; d += 256) {
        float xv = xr[d];
        const float4* wr = (const float4*)(Wg + (size_t)d * NE);
        float4 w0 = wr[0], w1 = wr[1];
        acc[0] += xv * w0.x; acc[1] += xv * w0.y; acc[2] += xv * w0.z; acc[3] += xv * w0.w;
        acc[4] += xv * w1.x; acc[5] += xv * w1.y; acc[6] += xv * w1.z; acc[7] += xv * w1.w;
    }
#pragma unroll
    for (int e = 0; e < NE; e++) red[tid][e] = acc[e];
    __syncthreads();
    for (int s = 128; s > 0; s >>= 1) {
        if (tid < s) {
#pragma unroll
            for (int e = 0; e < NE; e++) red[tid][e] += red[tid + s][e];
        }
        __syncthreads();
    }
    if (tid == 0) {
        float v[NE];
#pragma unroll
        for (int e = 0; e < NE; e++) v[e] = fmaxf(red[0][e], 0.f);
        int e0 = 0; float p0 = v[0];
        int e1 = -1; float p1 = -1.f;
#pragma unroll
        for (int e = 1; e < NE; e++) {
            if (v[e] > p0)      { p1 = p0; e1 = e0; p0 = v[e]; e0 = e; }
            else if (v[e] > p1) { p1 = v[e]; e1 = e; }
        }
        float w0 = 1.f / (1.f + expf(p1 - p0));
        g_sel[2*n] = e0; g_sel[2*n+1] = e1;
        g_w[2*n] = w0;   g_w[2*n+1] = 1.f - w0;
        atomicAdd(&g_cnt[e0], 1);
        atomicAdd(&g_cnt[e1], 1);
    }
}

__global__ void offsets_kernel() {
    if (threadIdx.x == 0) {
        int o = 0;
        for (int e = 0; e < NE; e++) { g_off[e] = o; o += g_cnt[e]; g_cur[e] = 0; }
    }
}

__global__ void scatter_kernel() {
    int n = blockIdx.x * blockDim.x + threadIdx.x;
    if (n >= N_TOK) return;
#pragma unroll
    for (int k = 0; k < 2; k++) {
        int e = g_sel[2*n + k];
        int p = atomicAdd(&g_cur[e], 1);
        int r = g_off[e] + p;
        g_perm[r] = n;
        g_wgt[r]  = g_w[2*n + k];
        g_rowpos[2*n + k] = r;
    }
}

// gather tokens -> expert-sorted fp16 buffer
__global__ void gather_kernel(const float* __restrict__ x) {
    int r = blockIdx.x, t = threadIdx.x;
    float4 v = ((const float4*)(x + (size_t)g_perm[r] * DIMD))[t];
    __half2* dst = (__half2*)(g_xh + (size_t)r * DIMD);
    dst[2*t]   = __floats2half2_rn(v.x, v.y);
    dst[2*t+1] = __floats2half2_rn(v.z, v.w);
}

// weight convert fp32 -> fp16 (elementwise, coalesced)
template<bool FIRST>
__global__ void convert_kernel(const float4* __restrict__ src, int n4) {
    __half2* dst = (__half2*)(FIRST ? g_w1h : g_w2h);
    for (int i = blockIdx.x * blockDim.x + threadIdx.x; i < n4; i += gridDim.x * blockDim.x) {
        float4 v = src[i];
        dst[2*i]   = __floats2half2_rn(v.x, v.y);
        dst[2*i+1] = __floats2half2_rn(v.z, v.w);
    }
}

// ---------------- fp16 HMMA GEMM ----------------
// CTA tile 128m x 256n, 8 warps (2m x 4n), warp tile 64x64, k-tile 64, 4-stage cp.async.
// A smem: [128 m][64 k] half, 128B rows, SW128 swizzle.
// B smem: [64 k][256 n] half, 512B rows, chunk^(k&7) swizzle; read via ldmatrix.trans.
template<int KD, int ND, bool FIRST>
__global__ __launch_bounds__(256, 1)
void gemm_hmma(const float* __restrict__ biasBase)
{
    extern __shared__ __align__(128) char smem[];
    const int e    = blockIdx.z;
    const int cnt  = g_cnt[e];
    const int row0 = blockIdx.x * 128;
    if (row0 >= cnt) return;
    const int base = g_off[e];
    const int col0 = blockIdx.y * 256;

    const __half* Asrc = FIRST ? g_xh : g_hh;
    const __half* B    = (FIRST ? g_w1h : g_w2h) + (size_t)e * KD * ND + col0;
    const float*  bias = biasBase + (size_t)e * ND + col0;

    const uint32_t sb  = smem_u32(smem);
    const int tid = threadIdx.x;
    const int wid = tid >> 5, lane = tid & 31;
    const int wm = wid >> 2, wn = wid & 3;
    const int lq = lane >> 2, lr = lane & 3;
    const int ls = lane & 7;

    // A row offsets (clamped)
    int aoff[4];
#pragma unroll
    for (int i = 0; i < 4; i++) {
        int r  = (tid >> 3) + 32 * i;
        int gr = row0 + r;
        int cr = (gr < cnt) ? gr : 0;
        aoff[i] = (base + cr) * KD;
    }
    const int aj = tid & 7;
    const int bc = tid & 31;
    const int bkl = tid >> 5;                // k low bits for B fill rows

    auto fill = [&](int kt) {
        char* st = smem + (size_t)(kt & 3) * STAGE;
        // A: 128 rows x 8 chunks of 16B
#pragma unroll
        for (int i = 0; i < 4; i++) {
            int r = (tid >> 3) + 32 * i;
            cp16(st + SW128(r * 128 + aj * 16), Asrc + aoff[i] + kt * 64 + aj * 8);
        }
        // B: 64 k-rows x 32 chunks of 16B (8 n each), swizzle chunk ^= k&7
#pragma unroll
        for (int i = 0; i < 8; i++) {
            int k = bkl + 8 * i;
            cp16(st + 16384 + k * 512 + ((bc ^ bkl) << 4),
                 B + (size_t)(kt * 64 + k) * ND + bc * 8);
        }
        asm volatile("cp.async.commit_group;");
    };

    const int KT = KD / 64;
    fill(0); fill(1); fill(2);

    float acc[4][8][4];
#pragma unroll
    for (int f = 0; f < 4; f++)
#pragma unroll
        for (int g = 0; g < 8; g++)
#pragma unroll
            for (int q = 0; q < 4; q++) acc[f][g][q] = 0.f;

    // fragment address precomputes
    const uint32_t aRowB = (uint32_t)(wm * 64 + ((lane >> 3) & 1) * 8 + ls) * 128;
    const uint32_t aCh   = (uint32_t)(lane >> 4);
    const uint32_t bRowB = (uint32_t)(((lane >> 3) & 1) * 8 + ls) * 512;
    const uint32_t bC0   = (uint32_t)(wn * 8 + (lane >> 4));

#pragma unroll 1
    for (int kt = 0; kt < KT; kt++) {
        const int rem = KT - 1 - kt;
        if (rem >= 2)      asm volatile("cp.async.wait_group 2;");
        else if (rem == 1) asm volatile("cp.async.wait_group 1;");
        else               asm volatile("cp.async.wait_group 0;");
        __syncthreads();
        if (kt + 3 < KT) fill(kt + 3);

        const uint32_t sA = sb + (uint32_t)(kt & 3) * STAGE;
        const uint32_t sB = sA + 16384;
#pragma unroll
        for (int ks = 0; ks < 4; ks++) {
            uint32_t a[4][4], b[4][4];
#pragma unroll
            for (int f = 0; f < 4; f++)
                ldm4(a[f], sA + aRowB + f * 2048 + (((2 * ks + aCh) ^ ls) << 4));
#pragma unroll
            for (int p = 0; p < 4; p++)
                ldm4t(b[p], sB + ks * 8192 + bRowB + (((bC0 + 2 * p) ^ ls) << 4));
#pragma unroll
            for (int f = 0; f < 4; f++)
#pragma unroll
                for (int g = 0; g < 8; g++)
                    mma16816(acc[f][g], a[f], &b[g >> 1][(g & 1) * 2]);
        }
    }

    // ---- epilogue: bias + relu + store ----
#pragma unroll
    for (int f = 0; f < 4; f++) {
        const int r0 = row0 + wm * 64 + f * 16 + lq;
        const int r1 = r0 + 8;
#pragma unroll
        for (int g = 0; g < 8; g++) {
            const int col = wn * 64 + g * 8 + 2 * lr;
            float2 bb = *(const float2*)(bias + col);
            float v00 = fmaxf(acc[f][g][0] + bb.x, 0.f);
            float v01 = fmaxf(acc[f][g][1] + bb.y, 0.f);
            float v10 = fmaxf(acc[f][g][2] + bb.x, 0.f);
            float v11 = fmaxf(acc[f][g][3] + bb.y, 0.f);
            if (FIRST) {
                if (r0 < cnt)
                    *(__half2*)(g_hh + (size_t)(base + r0) * ND + col0 + col) = __floats2half2_rn(v00, v01);
                if (r1 < cnt)
                    *(__half2*)(g_hh + (size_t)(base + r1) * ND + col0 + col) = __floats2half2_rn(v10, v11);
            } else {
                if (r0 < cnt)
                    *(float2*)(g_ybuf + (size_t)(base + r0) * ND + col0 + col) = make_float2(v00, v01);
                if (r1 < cnt)
                    *(float2*)(g_ybuf + (size_t)(base + r1) * ND + col0 + col) = make_float2(v10, v11);
            }
        }
    }
}

// ---------------- combine ----------------
__global__ void combine_kernel(float* __restrict__ out) {
    int gid = blockIdx.x * blockDim.x + threadIdx.x;
    if (gid >= N_TOK * OUTD / 4) return;
    int n = gid / (OUTD / 4);
    int c = (gid % (OUTD / 4)) * 4;
    int r0 = g_rowpos[2*n], r1 = g_rowpos[2*n + 1];
    float w0 = g_wgt[r0], w1 = g_wgt[r1];
    float4 y0 = *(const float4*)(g_ybuf + (size_t)r0 * OUTD + c);
    float4 y1 = *(const float4*)(g_ybuf + (size_t)r1 * OUTD + c);
    float4 o;
    o.x = w0*y0.x + w1*y1.x;
    o.y = w0*y0.y + w1*y1.y;
    o.z = w0*y0.z + w1*y1.z;
    o.w = w0*y0.w + w1*y1.w;
    *(float4*)(out + (size_t)n * OUTD + c) = o;
}

// ---------------- launch ----------------
extern "C" void kernel_launch(void* const* d_in, const int* in_sizes, int n_in,
                              void* d_out, int out_size) {
    const float* x  = (const float*)d_in[0];
    const float* Wg = (const float*)d_in[1];
    const float* W1 = (const float*)d_in[2];
    const float* b1 = (const float*)d_in[3];
    const float* W2 = (const float*)d_in[4];
    const float* b2 = (const float*)d_in[5];
    float* out = (float*)d_out;

    cudaFuncSetAttribute(gemm_hmma<DIMD, HID, true>,
                         cudaFuncAttributeMaxDynamicSharedMemorySize, SMEM_TOTAL);
    cudaFuncSetAttribute(gemm_hmma<HID, OUTD, false>,
                         cudaFuncAttributeMaxDynamicSharedMemorySize, SMEM_TOTAL);

    init_kernel<<<1, 32>>>();
    gate_kernel<<<N_TOK, 256>>>(x, Wg);
    offsets_kernel<<<1, 1>>>();
    scatter_kernel<<<(N_TOK + 255) / 256, 256>>>();
    gather_kernel<<<RMAX, 256>>>(x);

    convert_kernel<true ><<<8192, 256>>>((const float4*)W1, NE * DIMD * HID / 4);
    convert_kernel<false><<<8192, 256>>>((const float4*)W2, NE * HID * OUTD / 4);

    {
        dim3 grid(RMAX / 128, HID / 256, NE);   // (64, 16, 8), m fastest
        gemm_hmma<DIMD, HID, true><<<grid, 256, SMEM_TOTAL>>>(b1);
    }
    {
        dim3 grid(RMAX / 128, OUTD / 256, NE);  // (64, 4, 8)
        gemm_hmma<HID, OUTD, false><<<grid, 256, SMEM_TOTAL>>>(b2);
    }
    combine_kernel<<<(N_TOK * OUTD / 4 + 255) / 256, 256>>>(out);
}

// round 5
// speedup vs baseline: 5.5091x; 1.0526x over previous
#include <cuda_runtime.h>
#include <cuda_fp16.h>
#include <math.h>
#include <stdint.h>

#define N_TOK 4096
#define DIMD  1024
#define HID   4096
#define OUTD  1024
#define NE    8
#define RMAX  (2*N_TOK)

// ---------------- scratch (static device globals) ----------------
__device__ __half g_xh[(size_t)RMAX * DIMD];       // 16 MB gathered tokens (fp16)
__device__ __half g_hh[(size_t)RMAX * HID];        // 64 MB GEMM1 out (fp16)
__device__ float  g_ybuf[(size_t)RMAX * OUTD];     // 32 MB GEMM2 out (fp32)
__device__ __half g_w1h[(size_t)NE * DIMD * HID];  // 64 MB
__device__ __half g_w2h[(size_t)NE * HID * OUTD];  // 64 MB
__device__ int   g_perm[RMAX];
__device__ float g_wgt[RMAX];
__device__ int   g_rowpos[N_TOK * 2];
__device__ int   g_sel[N_TOK * 2];
__device__ float g_w[N_TOK * 2];
__device__ int   g_cnt[NE];
__device__ int   g_off[NE];

// ---------------- helpers ----------------
__device__ __forceinline__ void cp16(void* dst, const void* src) {
    unsigned sd = (unsigned)__cvta_generic_to_shared(dst);
    asm volatile("cp.async.cg.shared.global [%0], [%1], 16;" :: "r"(sd), "l"(src));
}
__device__ __forceinline__ uint32_t smem_u32(const void* p) {
    uint32_t a;
    asm("{ .reg .u64 t; cvta.to.shared.u64 t, %1; cvt.u32.u64 %0, t; }" : "=r"(a) : "l"(p));
    return a;
}
__device__ __forceinline__ void ldm4(uint32_t r[4], uint32_t addr) {
    asm volatile("ldmatrix.sync.aligned.m8n8.x4.shared.b16 {%0,%1,%2,%3}, [%4];"
        : "=r"(r[0]), "=r"(r[1]), "=r"(r[2]), "=r"(r[3]) : "r"(addr));
}
__device__ __forceinline__ void ldm4t(uint32_t r[4], uint32_t addr) {
    asm volatile("ldmatrix.sync.aligned.m8n8.x4.trans.shared.b16 {%0,%1,%2,%3}, [%4];"
        : "=r"(r[0]), "=r"(r[1]), "=r"(r[2]), "=r"(r[3]) : "r"(addr));
}
__device__ __forceinline__ void mma16816(float c[4], const uint32_t a[4], const uint32_t* b) {
    asm volatile("mma.sync.aligned.m16n8k16.row.col.f32.f16.f16.f32 "
        "{%0,%1,%2,%3}, {%4,%5,%6,%7}, {%8,%9}, {%0,%1,%2,%3};"
        : "+f"(c[0]), "+f"(c[1]), "+f"(c[2]), "+f"(c[3])
        : "r"(a[0]), "r"(a[1]), "r"(a[2]), "r"(a[3]), "r"(b[0]), "r"(b[1]));
}

#define SW128(x) ((x) ^ (((x) >> 3) & 0x70))
#define STAGE   49152
#define SMEM_TOTAL (4 * STAGE)

// ---------------- gate: warp-per-token, shuffle reduce, NO atomics ----------------
__global__ void gate_kernel(const float* __restrict__ x, const float* __restrict__ Wg) {
    const int wid  = threadIdx.x >> 5, lane = threadIdx.x & 31;
    const int n    = blockIdx.x * 8 + wid;
    const float* xr = x + (size_t)n * DIMD;

    float acc[NE];
#pragma unroll
    for (int e = 0; e < NE; e++) acc[e] = 0.f;
#pragma unroll 4
    for (int i = 0; i < DIMD / 32; i++) {
        int d = lane + 32 * i;
        float xv = xr[d];
        const float4* wr = (const float4*)(Wg + (size_t)d * NE);
        float4 w0 = wr[0], w1 = wr[1];
        acc[0] += xv * w0.x; acc[1] += xv * w0.y; acc[2] += xv * w0.z; acc[3] += xv * w0.w;
        acc[4] += xv * w1.x; acc[5] += xv * w1.y; acc[6] += xv * w1.z; acc[7] += xv * w1.w;
    }
#pragma unroll
    for (int e = 0; e < NE; e++) {
#pragma unroll
        for (int s = 16; s > 0; s >>= 1)
            acc[e] += __shfl_xor_sync(0xFFFFFFFFu, acc[e], s);
    }
    if (lane == 0) {
        float v[NE];
#pragma unroll
        for (int e = 0; e < NE; e++) v[e] = fmaxf(acc[e], 0.f);
        int e0 = 0; float p0 = v[0];
        int e1 = -1; float p1 = -1.f;
#pragma unroll
        for (int e = 1; e < NE; e++) {
            if (v[e] > p0)      { p1 = p0; e1 = e0; p0 = v[e]; e0 = e; }
            else if (v[e] > p1) { p1 = v[e]; e1 = e; }
        }
        float w0 = 1.f / (1.f + expf(p1 - p0));
        g_sel[2*n] = e0; g_sel[2*n+1] = e1;
        g_w[2*n] = w0;   g_w[2*n+1] = 1.f - w0;
    }
}

// ---------------- plan: counts + offsets + scatter, one block ----------------
__global__ void plan_kernel() {
    __shared__ int cnt[NE], off[NE], cur[NE];
    const int tid = threadIdx.x;
    if (tid < NE) { cnt[tid] = 0; cur[tid] = 0; }
    __syncthreads();
    for (int i = tid; i < RMAX; i += 1024) atomicAdd(&cnt[g_sel[i]], 1);
    __syncthreads();
    if (tid == 0) {
        int o = 0;
        for (int e = 0; e < NE; e++) { off[e] = o; g_off[e] = o; g_cnt[e] = cnt[e]; o += cnt[e]; }
    }
    __syncthreads();
    for (int i = tid; i < RMAX; i += 1024) {
        int e = g_sel[i];
        int p = atomicAdd(&cur[e], 1);
        int r = off[e] + p;
        g_perm[r]   = i >> 1;
        g_wgt[r]    = g_w[i];
        g_rowpos[i] = r;
    }
}

// gather tokens -> expert-sorted fp16 buffer
__global__ void gather_kernel(const float* __restrict__ x) {
    int r = blockIdx.x, t = threadIdx.x;
    float4 v = ((const float4*)(x + (size_t)g_perm[r] * DIMD))[t];
    __half2* dst = (__half2*)(g_xh + (size_t)r * DIMD);
    dst[2*t]   = __floats2half2_rn(v.x, v.y);
    dst[2*t+1] = __floats2half2_rn(v.z, v.w);
}

// weight convert fp32 -> fp16
template<bool FIRST>
__global__ void convert_kernel(const float4* __restrict__ src, int n4) {
    __half2* dst = (__half2*)(FIRST ? g_w1h : g_w2h);
    for (int i = blockIdx.x * blockDim.x + threadIdx.x; i < n4; i += gridDim.x * blockDim.x) {
        float4 v = src[i];
        dst[2*i]   = __floats2half2_rn(v.x, v.y);
        dst[2*i+1] = __floats2half2_rn(v.z, v.w);
    }
}

// ---------------- fp16 HMMA GEMM (at legacy-MMA ceiling) ----------------
template<int KD, int ND, bool FIRST>
__global__ __launch_bounds__(256, 1)
void gemm_hmma(const float* __restrict__ biasBase)
{
    extern __shared__ __align__(128) char smem[];
    const int e    = blockIdx.z;
    const int cnt  = g_cnt[e];
    const int row0 = blockIdx.x * 128;
    if (row0 >= cnt) return;
    const int base = g_off[e];
    const int col0 = blockIdx.y * 256;

    const __half* Asrc = FIRST ? g_xh : g_hh;
    const __half* B    = (FIRST ? g_w1h : g_w2h) + (size_t)e * KD * ND + col0;
    const float*  bias = biasBase + (size_t)e * ND + col0;

    const uint32_t sb  = smem_u32(smem);
    const int tid = threadIdx.x;
    const int wid = tid >> 5, lane = tid & 31;
    const int wm = wid >> 2, wn = wid & 3;
    const int lq = lane >> 2, lr = lane & 3;
    const int ls = lane & 7;

    int aoff[4];
#pragma unroll
    for (int i = 0; i < 4; i++) {
        int r  = (tid >> 3) + 32 * i;
        int gr = row0 + r;
        int cr = (gr < cnt) ? gr : 0;
        aoff[i] = (base + cr) * KD;
    }
    const int aj = tid & 7;
    const int bc = tid & 31;
    const int bkl = tid >> 5;

    auto fill = [&](int kt) {
        char* st = smem + (size_t)(kt & 3) * STAGE;
#pragma unroll
        for (int i = 0; i < 4; i++) {
            int r = (tid >> 3) + 32 * i;
            cp16(st + SW128(r * 128 + aj * 16), Asrc + aoff[i] + kt * 64 + aj * 8);
        }
#pragma unroll
        for (int i = 0; i < 8; i++) {
            int k = bkl + 8 * i;
            cp16(st + 16384 + k * 512 + ((bc ^ bkl) << 4),
                 B + (size_t)(kt * 64 + k) * ND + bc * 8);
        }
        asm volatile("cp.async.commit_group;");
    };

    const int KT = KD / 64;
    fill(0); fill(1); fill(2);

    float acc[4][8][4];
#pragma unroll
    for (int f = 0; f < 4; f++)
#pragma unroll
        for (int g = 0; g < 8; g++)
#pragma unroll
            for (int q = 0; q < 4; q++) acc[f][g][q] = 0.f;

    const uint32_t aRowB = (uint32_t)(wm * 64 + ((lane >> 3) & 1) * 8 + ls) * 128;
    const uint32_t aCh   = (uint32_t)(lane >> 4);
    const uint32_t bRowB = (uint32_t)(((lane >> 3) & 1) * 8 + ls) * 512;
    const uint32_t bC0   = (uint32_t)(wn * 8 + (lane >> 4));

#pragma unroll 1
    for (int kt = 0; kt < KT; kt++) {
        const int rem = KT - 1 - kt;
        if (rem >= 2)      asm volatile("cp.async.wait_group 2;");
        else if (rem == 1) asm volatile("cp.async.wait_group 1;");
        else               asm volatile("cp.async.wait_group 0;");
        __syncthreads();
        if (kt + 3 < KT) fill(kt + 3);

        const uint32_t sA = sb + (uint32_t)(kt & 3) * STAGE;
        const uint32_t sB = sA + 16384;
#pragma unroll
        for (int ks = 0; ks < 4; ks++) {
            uint32_t a[4][4], b[4][4];
#pragma unroll
            for (int f = 0; f < 4; f++)
                ldm4(a[f], sA + aRowB + f * 2048 + (((2 * ks + aCh) ^ ls) << 4));
#pragma unroll
            for (int p = 0; p < 4; p++)
                ldm4t(b[p], sB + ks * 8192 + bRowB + (((bC0 + 2 * p) ^ ls) << 4));
#pragma unroll
            for (int f = 0; f < 4; f++)
#pragma unroll
                for (int g = 0; g < 8; g++)
                    mma16816(acc[f][g], a[f], &b[g >> 1][(g & 1) * 2]);
        }
    }

#pragma unroll
    for (int f = 0; f < 4; f++) {
        const int r0 = row0 + wm * 64 + f * 16 + lq;
        const int r1 = r0 + 8;
#pragma unroll
        for (int g = 0; g < 8; g++) {
            const int col = wn * 64 + g * 8 + 2 * lr;
            float2 bb = *(const float2*)(bias + col);
            float v00 = fmaxf(acc[f][g][0] + bb.x, 0.f);
            float v01 = fmaxf(acc[f][g][1] + bb.y, 0.f);
            float v10 = fmaxf(acc[f][g][2] + bb.x, 0.f);
            float v11 = fmaxf(acc[f][g][3] + bb.y, 0.f);
            if (FIRST) {
                if (r0 < cnt)
                    *(__half2*)(g_hh + (size_t)(base + r0) * ND + col0 + col) = __floats2half2_rn(v00, v01);
                if (r1 < cnt)
                    *(__half2*)(g_hh + (size_t)(base + r1) * ND + col0 + col) = __floats2half2_rn(v10, v11);
            } else {
                if (r0 < cnt)
                    *(float2*)(g_ybuf + (size_t)(base + r0) * ND + col0 + col) = make_float2(v00, v01);
                if (r1 < cnt)
                    *(float2*)(g_ybuf + (size_t)(base + r1) * ND + col0 + col) = make_float2(v10, v11);
            }
        }
    }
}

// ---------------- combine ----------------
__global__ void combine_kernel(float* __restrict__ out) {
    int gid = blockIdx.x * blockDim.x + threadIdx.x;
    if (gid >= N_TOK * OUTD / 4) return;
    int n = gid / (OUTD / 4);
    int c = (gid % (OUTD / 4)) * 4;
    int r0 = g_rowpos[2*n], r1 = g_rowpos[2*n + 1];
    float w0 = g_wgt[r0], w1 = g_wgt[r1];
    float4 y0 = *(const float4*)(g_ybuf + (size_t)r0 * OUTD + c);
    float4 y1 = *(const float4*)(g_ybuf + (size_t)r1 * OUTD + c);
    float4 o;
    o.x = w0*y0.x + w1*y1.x;
    o.y = w0*y0.y + w1*y1.y;
    o.z = w0*y0.z + w1*y1.z;
    o.w = w0*y0.w + w1*y1.w;
    *(float4*)(out + (size_t)n * OUTD + c) = o;
}

// ---------------- launch: converts on a side stream, fork/join via events ----------------
extern "C" void kernel_launch(void* const* d_in, const int* in_sizes, int n_in,
                              void* d_out, int out_size) {
    const float* x  = (const float*)d_in[0];
    const float* Wg = (const float*)d_in[1];
    const float* W1 = (const float*)d_in[2];
    const float* b1 = (const float*)d_in[3];
    const float* W2 = (const float*)d_in[4];
    const float* b2 = (const float*)d_in[5];
    float* out = (float*)d_out;

    static cudaStream_t s1 = nullptr;
    static cudaEvent_t evFork = nullptr, evC1 = nullptr, evC2 = nullptr;
    static bool inited = false;
    if (!inited) {
        cudaStreamCreateWithFlags(&s1, cudaStreamNonBlocking);
        cudaEventCreateWithFlags(&evFork, cudaEventDisableTiming);
        cudaEventCreateWithFlags(&evC1,  cudaEventDisableTiming);
        cudaEventCreateWithFlags(&evC2,  cudaEventDisableTiming);
        cudaFuncSetAttribute(gemm_hmma<DIMD, HID, true>,
                             cudaFuncAttributeMaxDynamicSharedMemorySize, SMEM_TOTAL);
        cudaFuncSetAttribute(gemm_hmma<HID, OUTD, false>,
                             cudaFuncAttributeMaxDynamicSharedMemorySize, SMEM_TOTAL);
        inited = true;
    }

    // fork: side stream does the weight converts while main stream routes
    cudaEventRecord(evFork, 0);
    cudaStreamWaitEvent(s1, evFork, 0);
    convert_kernel<true ><<<4096, 256, 0, s1>>>((const float4*)W1, NE * DIMD * HID / 4);
    cudaEventRecord(evC1, s1);
    convert_kernel<false><<<4096, 256, 0, s1>>>((const float4*)W2, NE * HID * OUTD / 4);
    cudaEventRecord(evC2, s1);

    // main: routing chain
    gate_kernel<<<N_TOK / 8, 256>>>(x, Wg);
    plan_kernel<<<1, 1024>>>();
    gather_kernel<<<RMAX, 256>>>(x);

    // join convert1 -> GEMM1 (convert2 overlaps GEMM1)
    cudaStreamWaitEvent(0, evC1, 0);
    {
        dim3 grid(RMAX / 128, HID / 256, NE);
        gemm_hmma<DIMD, HID, true><<<grid, 256, SMEM_TOTAL>>>(b1);
    }
    cudaStreamWaitEvent(0, evC2, 0);
    {
        dim3 grid(RMAX / 128, OUTD / 256, NE);
        gemm_hmma<HID, OUTD, false><<<grid, 256, SMEM_TOTAL>>>(b2);
    }
    combine_kernel<<<(N_TOK * OUTD / 4 + 255) / 256, 256>>>(out);
}